// round 3
// baseline (speedup 1.0000x reference)
#include <cuda_runtime.h>
#include <math.h>
#include <stdint.h>

#define NTW   4096
#define NUSR  2048
#define NN    6144
#define NEDGE 98304
#define SEQL  32
#define EMB   300
#define HID   100
#define BSZ   2048
#define RALL  (NTW*SEQL)          /* 131072 */
#define N2D   37748736.0          /* NN*NN */
#define PWc   ((float)((37748736.0-104448.0)/104448.0))
#define CLIP_HI 0.99999988079071045f  /* fp32(1 - 1e-7) = 1 - 2^-23 */

// ---------------- scratch (device globals; allocation is forbidden) --------
__device__ float    g_Gi [(size_t)RALL*300];   // 157 MB (reused layer0/layer1)
__device__ float    g_Y0 [(size_t)RALL*HID];   // 52 MB layer-0 outputs
__device__ float    g_GH [NTW*300];
__device__ float    g_H  [NTW*HID];
__device__ float    g_T1 [NUSR*100];
__device__ float    g_UE [NUSR*100];
__device__ float    g_Xin[NN*100];
__device__ float    g_XW [NN*100];
__device__ float    g_Hc [NN*64];
__device__ float    g_MU [NN*100];
__device__ float    g_LV [NN*100];
__device__ float    g_Z  [NN*100];
__device__ float    g_deg[NN];
__device__ float    g_dis[NN];
__device__ int      g_rowtok[RALL];
__device__ unsigned g_Acnt[(size_t)NN*(NN/4)]; // packed u8 counts, 37.7 MB
__device__ double   g_acc[3];                  // sumP, sumWBCE, klsum

// ---------------- generic SGEMM: C[M,N] = gather(A) @ (bT? B[N,K]^T : B[K,N]) + bias
#define BM 128
#define BN 64
#define BK 16

__global__ __launch_bounds__(256) void sgemm(
    const float* __restrict__ A, const int* __restrict__ Arem,
    const float* __restrict__ B, const float* __restrict__ bias,
    float* __restrict__ C, int M, int N, int K, int bT, int act)
{
    __shared__ __align__(16) float As[BK][BM+4];
    __shared__ __align__(16) float Bs[BK][BN+4];
    __shared__ int rowmap[BM];
    int tid = threadIdx.x;
    int m0 = blockIdx.y * BM;
    int n0 = blockIdx.x * BN;
    if (tid < BM) {
        int r = m0 + tid;
        rowmap[tid] = (Arem != nullptr) ? ((r < M) ? Arem[r] : 0)
                                        : ((r < M) ? r : 0);
    }
    __syncthreads();

    float acc[8][4];
    #pragma unroll
    for (int i = 0; i < 8; i++)
        #pragma unroll
        for (int j = 0; j < 4; j++) acc[i][j] = 0.f;

    int ty = tid >> 4;   // 0..15 -> rows ty*8..ty*8+7
    int tx = tid & 15;   // cols tx*4..tx*4+3

    for (int k0 = 0; k0 < K; k0 += BK) {
        { // A tile: 128 rows x 16 k
            int arow = tid >> 1;
            int akq  = (tid & 1) * 8;
            int gr   = rowmap[arow];
            bool rok = (m0 + arow) < M;
            #pragma unroll
            for (int c = 0; c < 8; c++) {
                int kk = k0 + akq + c;
                float v = 0.f;
                if (rok && kk < K) v = A[(size_t)gr * K + kk];
                As[akq + c][arow] = v;
            }
        }
        if (bT) { // B[N][K]
            int col = tid >> 2;
            int kq  = (tid & 3) * 4;
            #pragma unroll
            for (int c = 0; c < 4; c++) {
                int kk = k0 + kq + c;
                float v = 0.f;
                if ((n0 + col) < N && kk < K) v = B[(size_t)(n0 + col) * K + kk];
                Bs[kq + c][col] = v;
            }
        } else { // B[K][N]
            int kr = tid >> 4;
            int cq = (tid & 15) * 4;
            #pragma unroll
            for (int c = 0; c < 4; c++) {
                int kk = k0 + kr, col = cq + c;
                float v = 0.f;
                if (kk < K && (n0 + col) < N) v = B[(size_t)kk * N + n0 + col];
                Bs[kr][col] = v;
            }
        }
        __syncthreads();
        #pragma unroll
        for (int k = 0; k < BK; k++) {
            float4 a0 = *(const float4*)&As[k][ty*8];
            float4 a1 = *(const float4*)&As[k][ty*8+4];
            float4 b0 = *(const float4*)&Bs[k][tx*4];
            float av[8] = {a0.x,a0.y,a0.z,a0.w,a1.x,a1.y,a1.z,a1.w};
            float bv[4] = {b0.x,b0.y,b0.z,b0.w};
            #pragma unroll
            for (int i = 0; i < 8; i++)
                #pragma unroll
                for (int j = 0; j < 4; j++)
                    acc[i][j] += av[i] * bv[j];
        }
        __syncthreads();
    }
    #pragma unroll
    for (int i = 0; i < 8; i++) {
        int m = m0 + ty*8 + i;
        if (m < M) {
            #pragma unroll
            for (int j = 0; j < 4; j++) {
                int n = n0 + tx*4 + j;
                if (n < N) {
                    float v = acc[i][j];
                    if (bias) v += bias[n];
                    if (act == 1) v = fmaxf(v, 0.f);
                    C[(size_t)m * N + n] = v;
                }
            }
        }
    }
}

// ---------------- small kernels --------------------------------------------
__global__ void k_zero_u(unsigned* p, size_t n) {
    size_t i = (size_t)blockIdx.x * blockDim.x + threadIdx.x;
    size_t st = (size_t)gridDim.x * blockDim.x;
    for (; i < n; i += st) p[i] = 0u;
}
__global__ void k_zero_fd(float* f, int nf, double* d, int nd) {
    int i = blockIdx.x * 256 + threadIdx.x;
    if (i < nf) f[i] = 0.f;
    if (i < nd) d[i] = 0.0;
}
__global__ void k_scatter_cnt(const int* __restrict__ src, const int* __restrict__ dst,
                              unsigned* __restrict__ cnt, float* __restrict__ deg) {
    int e = blockIdx.x * 256 + threadIdx.x;
    if (e >= NEDGE) return;
    int s = src[e], d = dst[e];
    size_t idx = (size_t)s * NN + d;
    atomicAdd(&cnt[idx >> 2], 1u << ((idx & 3) * 8));
    atomicAdd(&deg[d], 1.f);
}
__global__ void k_dis(const float* __restrict__ deg, float* __restrict__ dis) {
    int i = blockIdx.x * 256 + threadIdx.x;
    if (i < NN) dis[i] = rsqrtf(deg[i] + 1.f);
}
__global__ void k_rowtok(const int* __restrict__ gnf, int* __restrict__ rowtok) {
    int r = blockIdx.x * 256 + threadIdx.x;
    if (r >= RALL) return;
    int t = r & (NTW - 1);
    int s = r >> 12;
    rowtok[r] = gnf[t * SEQL + s];
}
__global__ void k_copy(float* __restrict__ dst, const float* __restrict__ src, int n) {
    int i = blockIdx.x * 256 + threadIdx.x;
    if (i < n) dst[i] = src[i];
}
__global__ void k_gate(const float* __restrict__ Gi, const float* __restrict__ GH,
                       float* __restrict__ H, float* __restrict__ Y) {
    int idx = blockIdx.x * 256 + threadIdx.x;
    if (idx >= NTW * HID) return;
    int t = idx / HID, c = idx - t * HID;
    const float* gi = Gi + (size_t)t * 300;
    const float* gh = GH + (size_t)t * 300;
    float h = H[idx];
    float r = 1.f / (1.f + expf(-(gi[c]         + gh[c])));
    float z = 1.f / (1.f + expf(-(gi[c + HID]   + gh[c + HID])));
    float n = tanhf(gi[c + 2*HID] + r * gh[c + 2*HID]);
    float hn = (1.f - z) * n + z * h;
    H[idx] = hn;
    if (Y) Y[idx] = hn;
}
__global__ void k_xin(const float* __restrict__ H, const float* __restrict__ UE,
                      float* __restrict__ Xin) {
    int i = blockIdx.x * 256 + threadIdx.x;
    if (i >= NN * 100) return;
    int n = i / 100, c = i - n * 100;
    float v;
    if (n < BSZ)             v = H[i];
    else if (n < BSZ + NUSR) v = UE[(size_t)(n - BSZ) * 100 + c];
    else                     v = H[(size_t)(n - NUSR) * 100 + c];
    Xin[i] = v;
}
__global__ void k_ginit(const float* __restrict__ xw, const float* __restrict__ dis,
                        const float* __restrict__ b, float* __restrict__ agg, int C) {
    int i = blockIdx.x * 256 + threadIdx.x;
    if (i >= NN * C) return;
    int n = i / C, c = i - n * C;
    float d = dis[n];
    agg[i] = xw[i] * d * d + b[c];
}
__global__ void k_gscat(const float* __restrict__ xw, const int* __restrict__ src,
                        const int* __restrict__ dst, const float* __restrict__ dis,
                        float* __restrict__ agg, int C) {
    int i = blockIdx.x * 256 + threadIdx.x;
    if (i >= NEDGE * C) return;
    int e = i / C, c = i - e * C;
    int s = src[e], d = dst[e];
    atomicAdd(&agg[(size_t)d * C + c], xw[(size_t)s * C + c] * dis[s] * dis[d]);
}
__global__ void k_act(float* __restrict__ x, int n, int mode) {
    int i = blockIdx.x * 256 + threadIdx.x;
    if (i >= n) return;
    float v = x[i];
    x[i] = mode ? fmaxf(v, 0.f) : (v > 0.f ? v : expm1f(v));
}
__global__ void k_rep(const float* __restrict__ MU, const float* __restrict__ LV,
                      const float* __restrict__ eps, float* __restrict__ Z) {
    int i = blockIdx.x * 256 + threadIdx.x;
    if (i >= NN * 100) return;
    Z[i] = MU[i] + expf(LV[i] * 0.5f) * eps[i];
}
__global__ void k_kl(const float* __restrict__ MU, const float* __restrict__ LV,
                     double* __restrict__ acc) {
    __shared__ double red[256];
    int i = blockIdx.x * 256 + threadIdx.x;
    double v = 0.0;
    if (i < NN * 100) {
        float mu = MU[i], lv = LV[i];
        v = (double)(-0.5f * (1.f + lv - mu * mu - expf(lv)));
    }
    red[threadIdx.x] = v; __syncthreads();
    for (int o = 128; o > 0; o >>= 1) {
        if (threadIdx.x < o) red[threadIdx.x] += red[threadIdx.x + o];
        __syncthreads();
    }
    if (threadIdx.x == 0) atomicAdd(&acc[2], red[0]);
}
__global__ void k_outz(const float* __restrict__ Z, float* __restrict__ out) {
    int i = blockIdx.x * 256 + threadIdx.x;
    if (i < BSZ * 100) out[i] = Z[i];
}
// Z @ Z^T tile loss: never materializes A_pred
__global__ __launch_bounds__(256) void k_zzt(const float* __restrict__ Z,
                                             const unsigned* __restrict__ cnt,
                                             double* __restrict__ acc) {
    __shared__ float Zi[32][105];
    __shared__ float Zj[32][105];
    __shared__ double red[256];
    int bi = blockIdx.y * 32, bj = blockIdx.x * 32;
    for (int idx = threadIdx.x; idx < 32 * 100; idx += 256) {
        int r = idx / 100, c = idx - r * 100;
        Zi[r][c] = Z[(size_t)(bi + r) * 100 + c];
        Zj[r][c] = Z[(size_t)(bj + r) * 100 + c];
    }
    __syncthreads();
    double sp = 0.0, sw = 0.0;
    #pragma unroll
    for (int q = 0; q < 4; q++) {
        int cell = threadIdx.x + q * 256;
        int ii = cell >> 5, jj = cell & 31;
        float zz = 0.f;
        #pragma unroll 4
        for (int k = 0; k < 100; k++) zz += Zi[ii][k] * Zj[jj][k];
        float s = 1.f / (1.f + expf(-zz));
        sp += (double)s;
        float p = fminf(fmaxf(s, 1e-7f), CLIP_HI);
        int i = bi + ii, j = bj + jj;
        size_t idx = (size_t)i * NN + j;
        unsigned w4 = cnt[idx >> 2];
        float ag = (float)((w4 >> ((idx & 3) * 8)) & 0xFFu) + ((i == j) ? 1.f : 0.f);
        float wgt = (ag == 1.f) ? PWc : 1.f;
        float bce = -(ag * logf(p) + (1.f - ag) * log1pf(-p));
        sw += (double)(wgt * bce);
    }
    red[threadIdx.x] = sp; __syncthreads();
    for (int o = 128; o > 0; o >>= 1) {
        if (threadIdx.x < o) red[threadIdx.x] += red[threadIdx.x + o];
        __syncthreads();
    }
    if (threadIdx.x == 0) atomicAdd(&acc[0], red[0]);
    __syncthreads();
    red[threadIdx.x] = sw; __syncthreads();
    for (int o = 128; o > 0; o >>= 1) {
        if (threadIdx.x < o) red[threadIdx.x] += red[threadIdx.x + o];
        __syncthreads();
    }
    if (threadIdx.x == 0) atomicAdd(&acc[1], red[0]);
}
__global__ void k_fin(const double* __restrict__ acc, float* __restrict__ out) {
    double sumP = acc[0], sumWB = acc[1];
    double norm = N2D / ((N2D - sumP) * 2.0);
    out[BSZ * 100]     = (float)(acc[2] / (double)NN);      // kl_loss
    out[BSZ * 100 + 1] = (float)(norm * (sumWB / N2D));     // rec_loss
}

// ---------------- host launch ----------------------------------------------
extern "C" void kernel_launch(void* const* d_in, const int* in_sizes, int n_in,
                              void* d_out, int out_size) {
    const float* user_feats = (const float*)d_in[0];
    const int*   gnf        = (const int*)  d_in[1];
    const int*   eidx       = (const int*)  d_in[2];
    const float* h0         = (const float*)d_in[4];
    const float* eps        = (const float*)d_in[5];
    const float* emb        = (const float*)d_in[6];
    const float* mw1 = (const float*)d_in[7],  *mb1 = (const float*)d_in[8];
    const float* mw2 = (const float*)d_in[9],  *mb2 = (const float*)d_in[10];
    const float* wih0 = (const float*)d_in[11], *whh0 = (const float*)d_in[12];
    const float* bih0 = (const float*)d_in[13], *bhh0 = (const float*)d_in[14];
    const float* wih1 = (const float*)d_in[15], *whh1 = (const float*)d_in[16];
    const float* bih1 = (const float*)d_in[17], *bhh1 = (const float*)d_in[18];
    const float* c1w = (const float*)d_in[19], *c1b = (const float*)d_in[20];
    const float* cmw = (const float*)d_in[21], *cmb = (const float*)d_in[22];
    const float* clw = (const float*)d_in[23], *clb = (const float*)d_in[24];
    float* out = (float*)d_out;
    const int* srcp = eidx;
    const int* dstp = eidx + NEDGE;

    void* p;
    cudaGetSymbolAddress(&p, g_Gi);  float* Gi  = (float*)p;
    cudaGetSymbolAddress(&p, g_Y0);  float* Y0  = (float*)p;
    cudaGetSymbolAddress(&p, g_GH);  float* GH  = (float*)p;
    cudaGetSymbolAddress(&p, g_H);   float* H   = (float*)p;
    cudaGetSymbolAddress(&p, g_T1);  float* T1  = (float*)p;
    cudaGetSymbolAddress(&p, g_UE);  float* UE  = (float*)p;
    cudaGetSymbolAddress(&p, g_Xin); float* Xin = (float*)p;
    cudaGetSymbolAddress(&p, g_XW);  float* XW  = (float*)p;
    cudaGetSymbolAddress(&p, g_Hc);  float* Hc  = (float*)p;
    cudaGetSymbolAddress(&p, g_MU);  float* MU  = (float*)p;
    cudaGetSymbolAddress(&p, g_LV);  float* LV  = (float*)p;
    cudaGetSymbolAddress(&p, g_Z);   float* Z   = (float*)p;
    cudaGetSymbolAddress(&p, g_deg); float* deg = (float*)p;
    cudaGetSymbolAddress(&p, g_dis); float* dis = (float*)p;
    cudaGetSymbolAddress(&p, g_rowtok); int* rowtok = (int*)p;
    cudaGetSymbolAddress(&p, g_Acnt);   unsigned* Acnt = (unsigned*)p;
    cudaGetSymbolAddress(&p, g_acc);    double* acc = (double*)p;

    // graph structure + zeroing
    k_zero_u<<<2048, 256>>>(Acnt, (size_t)NN * (NN / 4));
    k_zero_fd<<<(NN + 255) / 256, 256>>>(deg, NN, acc, 3);
    k_scatter_cnt<<<(NEDGE + 255) / 256, 256>>>(srcp, dstp, Acnt, deg);
    k_dis<<<(NN + 255) / 256, 256>>>(deg, dis);
    k_rowtok<<<(RALL + 255) / 256, 256>>>(gnf, rowtok);

    // hoisted layer-0 input gates: gather(embed) @ Wih0^T + bih0
    sgemm<<<dim3(5, 1024), 256>>>(emb, rowtok, wih0, bih0, Gi, RALL, 300, 300, 1, 0);

    // user encoder MLP
    sgemm<<<dim3(2, 16), 256>>>(user_feats, nullptr, mw1, mb1, T1, NUSR, 100, 9, 0, 1);
    sgemm<<<dim3(2, 16), 256>>>(T1, nullptr, mw2, mb2, UE, NUSR, 100, 100, 0, 0);

    // GRU layer 0
    k_copy<<<1600, 256>>>(H, h0, NTW * HID);
    for (int s = 0; s < SEQL; s++) {
        sgemm<<<dim3(5, 32), 256>>>(H, nullptr, whh0, bhh0, GH, NTW, 300, HID, 1, 0);
        k_gate<<<1600, 256>>>(Gi + (size_t)s * NTW * 300, GH, H,
                              Y0 + (size_t)s * NTW * HID);
    }
    // hoisted layer-1 input gates
    sgemm<<<dim3(5, 1024), 256>>>(Y0, nullptr, wih1, bih1, Gi, RALL, 300, HID, 1, 0);
    // GRU layer 1
    k_copy<<<1600, 256>>>(H, h0 + NTW * HID, NTW * HID);
    for (int s = 0; s < SEQL; s++) {
        sgemm<<<dim3(5, 32), 256>>>(H, nullptr, whh1, bhh1, GH, NTW, 300, HID, 1, 0);
        k_gate<<<1600, 256>>>(Gi + (size_t)s * NTW * 300, GH, H, nullptr);
    }

    // x_input = concat(hn[:bs], ue, hn[bs:])
    k_xin<<<(NN * 100 + 255) / 256, 256>>>(H, UE, Xin);

    // conv1 -> elu
    sgemm<<<dim3(1, 48), 256>>>(Xin, nullptr, c1w, nullptr, XW, NN, 64, 100, 0, 0);
    k_ginit<<<(NN * 64 + 255) / 256, 256>>>(XW, dis, c1b, Hc, 64);
    k_gscat<<<(NEDGE * 64 + 255) / 256, 256>>>(XW, srcp, dstp, dis, Hc, 64);
    k_act<<<(NN * 64 + 255) / 256, 256>>>(Hc, NN * 64, 0);

    // convmu -> relu
    sgemm<<<dim3(2, 48), 256>>>(Hc, nullptr, cmw, nullptr, XW, NN, 100, 64, 0, 0);
    k_ginit<<<(NN * 100 + 255) / 256, 256>>>(XW, dis, cmb, MU, 100);
    k_gscat<<<(NEDGE * 100 + 255) / 256, 256>>>(XW, srcp, dstp, dis, MU, 100);
    k_act<<<(NN * 100 + 255) / 256, 256>>>(MU, NN * 100, 1);

    // convlv -> relu
    sgemm<<<dim3(2, 48), 256>>>(Hc, nullptr, clw, nullptr, XW, NN, 100, 64, 0, 0);
    k_ginit<<<(NN * 100 + 255) / 256, 256>>>(XW, dis, clb, LV, 100);
    k_gscat<<<(NEDGE * 100 + 255) / 256, 256>>>(XW, srcp, dstp, dis, LV, 100);
    k_act<<<(NN * 100 + 255) / 256, 256>>>(LV, NN * 100, 1);

    // reparametrize, KL, outputs
    k_rep<<<(NN * 100 + 255) / 256, 256>>>(MU, LV, eps, Z);
    k_kl<<<(NN * 100 + 255) / 256, 256>>>(MU, LV, acc);
    k_outz<<<(BSZ * 100 + 255) / 256, 256>>>(Z, out);
    k_zzt<<<dim3(192, 192), 256>>>(Z, Acnt, acc);
    k_fin<<<1, 1>>>(acc, out);
}

// round 4
// speedup vs baseline: 1.4847x; 1.4847x over previous
#include <cuda_runtime.h>
#include <math.h>
#include <stdint.h>

#define NTW   4096
#define NUSR  2048
#define NN    6144
#define NEDGE 98304
#define SEQL  32
#define EMB   300
#define HID   100
#define BSZ   2048
#define VOCAB 50000
#define RALL  (NTW*SEQL)          /* 131072 */
#define N2D   37748736.0          /* NN*NN */
#define PWc   ((float)((37748736.0-104448.0)/104448.0))
#define CLIP_HI 0.99999988079071045f  /* fp32(1 - 1e-7) = 1 - 2^-23 */

// ---------------- scratch ---------------------------------------------------
__device__ float    g_Gi [(size_t)RALL*300];   // E2G (60MB) then Gi1 (157MB)
__device__ float    g_Y0 [(size_t)RALL*HID];   // layer-0 outputs (52MB)
__device__ float    g_T1 [NUSR*100];
__device__ float    g_Xin[NN*100];
__device__ float    g_XW [NN*100];
__device__ float    g_Hc [NN*64];
__device__ float    g_MU [NN*100];
__device__ float    g_LV [NN*100];
__device__ float    g_Z  [NN*100];
__device__ float    g_deg[NN];
__device__ float    g_dis[NN];
__device__ unsigned g_Acnt[(size_t)NN*(NN/4)]; // packed u8 counts, 37.7MB
__device__ double   g_accP[96];
__device__ double   g_accW[96];
__device__ double   g_accK[64];

// ---------------- generic SGEMM ---------------------------------------------
#define BM 128
#define BN 64
#define BK 16

__global__ __launch_bounds__(256) void sgemm(
    const float* __restrict__ A,
    const float* __restrict__ B, const float* __restrict__ bias,
    float* __restrict__ C, int M, int N, int K, int bT, int act)
{
    __shared__ __align__(16) float As[BK][BM+4];
    __shared__ __align__(16) float Bs[BK][BN+4];
    int tid = threadIdx.x;
    int m0 = blockIdx.y * BM;
    int n0 = blockIdx.x * BN;

    float acc[8][4];
    #pragma unroll
    for (int i = 0; i < 8; i++)
        #pragma unroll
        for (int j = 0; j < 4; j++) acc[i][j] = 0.f;

    int ty = tid >> 4;
    int tx = tid & 15;

    for (int k0 = 0; k0 < K; k0 += BK) {
        {
            int arow = tid >> 1;
            int akq  = (tid & 1) * 8;
            int gm   = m0 + arow;
            bool rok = gm < M;
            #pragma unroll
            for (int c = 0; c < 8; c++) {
                int kk = k0 + akq + c;
                float v = 0.f;
                if (rok && kk < K) v = A[(size_t)gm * K + kk];
                As[akq + c][arow] = v;
            }
        }
        if (bT) {
            int col = tid >> 2;
            int kq  = (tid & 3) * 4;
            #pragma unroll
            for (int c = 0; c < 4; c++) {
                int kk = k0 + kq + c;
                float v = 0.f;
                if ((n0 + col) < N && kk < K) v = B[(size_t)(n0 + col) * K + kk];
                Bs[kq + c][col] = v;
            }
        } else {
            int kr = tid >> 4;
            int cq = (tid & 15) * 4;
            #pragma unroll
            for (int c = 0; c < 4; c++) {
                int kk = k0 + kr, col = cq + c;
                float v = 0.f;
                if (kk < K && (n0 + col) < N) v = B[(size_t)kk * N + n0 + col];
                Bs[kr][col] = v;
            }
        }
        __syncthreads();
        #pragma unroll
        for (int k = 0; k < BK; k++) {
            float4 a0 = *(const float4*)&As[k][ty*8];
            float4 a1 = *(const float4*)&As[k][ty*8+4];
            float4 b0 = *(const float4*)&Bs[k][tx*4];
            float av[8] = {a0.x,a0.y,a0.z,a0.w,a1.x,a1.y,a1.z,a1.w};
            float bv[4] = {b0.x,b0.y,b0.z,b0.w};
            #pragma unroll
            for (int i = 0; i < 8; i++)
                #pragma unroll
                for (int j = 0; j < 4; j++)
                    acc[i][j] += av[i] * bv[j];
        }
        __syncthreads();
    }
    #pragma unroll
    for (int i = 0; i < 8; i++) {
        int m = m0 + ty*8 + i;
        if (m < M) {
            #pragma unroll
            for (int j = 0; j < 4; j++) {
                int n = n0 + tx*4 + j;
                if (n < N) {
                    float v = acc[i][j];
                    if (bias) v += bias[n];
                    if (act == 1) v = fmaxf(v, 0.f);
                    C[(size_t)m * N + n] = v;
                }
            }
        }
    }
}

// ---------------- persistent GRU layer --------------------------------------
// 128 blocks x 256 threads; each block owns 32 rows through all 32 steps.
// smem: sW[100][320] Whh^T padded, sG[32][320], sH[32][104], sB[320]
#define GRU_SMEM 183552

template<int LAYER>
__global__ __launch_bounds__(256) void gru_persist(
    const float* __restrict__ GIsrc,   // L0: E2G[V,300]; L1: Gi1[RALL,300]
    const int*   __restrict__ gnf,     // L0 only
    const float* __restrict__ whh, const float* __restrict__ bhh,
    const float* __restrict__ h0,
    float* __restrict__ Yout)          // L0: Y0[RALL,100]; L1: Xin (scattered)
{
    extern __shared__ float sm[];
    float* sW = sm;                    // 32000
    float* sG = sm + 32000;            // 10240
    float* sH = sm + 42240;            // 3328
    float* sB = sm + 45568;            // 320
    int tid = threadIdx.x;
    int rowbase = blockIdx.x * 32;

    for (int idx = tid; idx < 30000; idx += 256) {
        int c = idx / 100, k = idx - c * 100;
        sW[k*320 + c] = whh[idx];
    }
    for (int idx = tid; idx < 2000; idx += 256) {
        int k = idx / 20, c = 300 + idx - (idx/20)*20;
        sW[k*320 + c] = 0.f;
    }
    for (int idx = tid; idx < 320; idx += 256) sB[idx] = (idx < 300) ? bhh[idx] : 0.f;
    for (int idx = tid; idx < 3200; idx += 256) {
        int r = idx / 100, c = idx - r * 100;
        sH[r*104 + c] = h0[(size_t)(rowbase + r)*100 + c];
    }
    __syncthreads();

    int r0 = (tid >> 6) * 8;      // 4 groups of 8 rows
    int c0 = (tid & 63) * 5;      // 64 groups of 5 cols (320)

    for (int s = 0; s < SEQL; s++) {
        float acc[8][5];
        #pragma unroll
        for (int e = 0; e < 8; e++)
            #pragma unroll
            for (int j = 0; j < 5; j++) acc[e][j] = 0.f;

        #pragma unroll 2
        for (int k = 0; k < 100; k++) {
            float hv[8];
            #pragma unroll
            for (int e = 0; e < 8; e++) hv[e] = sH[(r0+e)*104 + k];
            float w[5];
            #pragma unroll
            for (int j = 0; j < 5; j++) w[j] = sW[k*320 + c0 + j];
            #pragma unroll
            for (int e = 0; e < 8; e++)
                #pragma unroll
                for (int j = 0; j < 5; j++) acc[e][j] += hv[e] * w[j];
        }
        #pragma unroll
        for (int e = 0; e < 8; e++)
            #pragma unroll
            for (int j = 0; j < 5; j++) sG[(r0+e)*320 + c0 + j] = acc[e][j];
        __syncthreads();

        for (int ii = tid; ii < 3200; ii += 256) {
            int r = ii / 100, c = ii - r * 100;
            int grow = rowbase + r;
            const float* gi;
            if (LAYER == 0) {
                int tok = gnf[grow * SEQL + s];
                gi = GIsrc + (size_t)tok * 300;
            } else {
                gi = GIsrc + ((size_t)s * NTW + grow) * 300;
            }
            float hr  = sG[r*320 + c]       + sB[c];
            float hz  = sG[r*320 + c + 100] + sB[c+100];
            float hnn = sG[r*320 + c + 200] + sB[c+200];
            float h   = sH[r*104 + c];
            float rg = 1.f / (1.f + expf(-(gi[c]       + hr)));
            float zg = 1.f / (1.f + expf(-(gi[c+100]   + hz)));
            float ng = tanhf(gi[c+200] + rg * hnn);
            float hn = (1.f - zg) * ng + zg * h;
            sH[r*104 + c] = hn;
            if (LAYER == 0)
                Yout[((size_t)s * NTW + grow) * 100 + c] = hn;
        }
        __syncthreads();
    }
    if (LAYER == 1) {
        for (int ii = tid; ii < 3200; ii += 256) {
            int r = ii / 100, c = ii - r * 100;
            int grow = rowbase + r;
            int orow = (grow < BSZ) ? grow : grow + NUSR;
            Yout[(size_t)orow * 100 + c] = sH[r*104 + c];
        }
    }
}

// ---------------- small kernels ----------------------------------------------
__global__ void k_scatter_cnt(const int* __restrict__ src, const int* __restrict__ dst,
                              unsigned* __restrict__ cnt, float* __restrict__ deg) {
    int e = blockIdx.x * 256 + threadIdx.x;
    if (e >= NEDGE) return;
    int s = src[e], d = dst[e];
    size_t idx = (size_t)s * NN + d;
    atomicAdd(&cnt[idx >> 2], 1u << ((idx & 3) * 8));
    atomicAdd(&deg[d], 1.f);
}
__global__ void k_dis(const float* __restrict__ deg, float* __restrict__ dis) {
    int i = blockIdx.x * 256 + threadIdx.x;
    if (i < NN) dis[i] = rsqrtf(deg[i] + 1.f);
}
__global__ void k_ginit(const float* __restrict__ xw, const float* __restrict__ dis,
                        const float* __restrict__ b, float* __restrict__ agg, int C) {
    int i = blockIdx.x * 256 + threadIdx.x;
    if (i >= NN * C) return;
    int n = i / C, c = i - n * C;
    float d = dis[n];
    agg[i] = xw[i] * d * d + b[c];
}
__global__ void k_gscat(const float* __restrict__ xw, const int* __restrict__ src,
                        const int* __restrict__ dst, const float* __restrict__ dis,
                        float* __restrict__ agg, int C) {
    int i = blockIdx.x * 256 + threadIdx.x;
    if (i >= NEDGE * C) return;
    int e = i / C, c = i - e * C;
    int s = src[e], d = dst[e];
    atomicAdd(&agg[(size_t)d * C + c], xw[(size_t)s * C + c] * dis[s] * dis[d]);
}
__global__ void k_act(float* __restrict__ x, int n, int mode) {
    int i = blockIdx.x * 256 + threadIdx.x;
    if (i >= n) return;
    float v = x[i];
    x[i] = mode ? fmaxf(v, 0.f) : (v > 0.f ? v : expm1f(v));
}
__global__ void k_rep(const float* __restrict__ MU, const float* __restrict__ LV,
                      const float* __restrict__ eps, float* __restrict__ Z,
                      float* __restrict__ out) {
    int i = blockIdx.x * 256 + threadIdx.x;
    if (i >= NN * 100) return;
    float z = MU[i] + expf(LV[i] * 0.5f) * eps[i];
    Z[i] = z;
    if (i < BSZ * 100) out[i] = z;
}
__global__ void k_kl(const float* __restrict__ MU, const float* __restrict__ LV,
                     double* __restrict__ accK) {
    __shared__ double red[256];
    double v = 0.0;
    for (int i = blockIdx.x * 256 + threadIdx.x; i < NN * 100; i += 512 * 256) {
        float mu = MU[i], lv = LV[i];
        v += (double)(-0.5f * (1.f + lv - mu * mu - expf(lv)));
    }
    red[threadIdx.x] = v; __syncthreads();
    for (int o = 128; o > 0; o >>= 1) {
        if (threadIdx.x < o) red[threadIdx.x] += red[threadIdx.x + o];
        __syncthreads();
    }
    if (threadIdx.x == 0) atomicAdd(&accK[blockIdx.x & 63], red[0]);
}

// ---------------- Z@Z^T loss, 64x64 tiles ------------------------------------
#define ZZT_SMEM 51200
__global__ __launch_bounds__(256) void k_zzt2(const float* __restrict__ Z,
                                              const unsigned* __restrict__ cnt,
                                              double* __restrict__ accP,
                                              double* __restrict__ accW) {
    extern __shared__ float zsm[];
    float* Zi  = zsm;          // [64][100]
    float* ZjT = zsm + 6400;   // [100][64]
    int tid = threadIdx.x;
    int bi = blockIdx.y * 64, bj = blockIdx.x * 64;

    for (int f = tid; f < 6400; f += 256) {
        int r = f / 100, c = f - r * 100;
        Zi[f] = Z[(size_t)(bi + r) * 100 + c];
    }
    for (int f = tid; f < 6400; f += 256) {
        int k = f >> 6, j = f & 63;
        ZjT[f] = Z[(size_t)(bj + j) * 100 + k];
    }
    __syncthreads();

    int ty = tid >> 4, tx = tid & 15;
    int i0 = ty * 4, j0 = tx * 4;
    float acc[4][4];
    #pragma unroll
    for (int e = 0; e < 4; e++)
        #pragma unroll
        for (int j = 0; j < 4; j++) acc[e][j] = 0.f;

    #pragma unroll 4
    for (int k = 0; k < 100; k++) {
        float4 b = *(const float4*)&ZjT[k * 64 + j0];
        float a0 = Zi[(i0+0)*100 + k];
        float a1 = Zi[(i0+1)*100 + k];
        float a2 = Zi[(i0+2)*100 + k];
        float a3 = Zi[(i0+3)*100 + k];
        acc[0][0]+=a0*b.x; acc[0][1]+=a0*b.y; acc[0][2]+=a0*b.z; acc[0][3]+=a0*b.w;
        acc[1][0]+=a1*b.x; acc[1][1]+=a1*b.y; acc[1][2]+=a1*b.z; acc[1][3]+=a1*b.w;
        acc[2][0]+=a2*b.x; acc[2][1]+=a2*b.y; acc[2][2]+=a2*b.z; acc[2][3]+=a2*b.w;
        acc[3][0]+=a3*b.x; acc[3][1]+=a3*b.y; acc[3][2]+=a3*b.z; acc[3][3]+=a3*b.w;
    }

    double sp = 0.0, sw = 0.0;
    #pragma unroll
    for (int e = 0; e < 4; e++) {
        int i = bi + i0 + e;
        unsigned word = cnt[(size_t)i * (NN/4) + (unsigned)((bj >> 2) + tx)];
        #pragma unroll
        for (int j = 0; j < 4; j++) {
            int jg = bj + j0 + j;
            float zz = acc[e][j];
            float sg = 1.f / (1.f + expf(-zz));
            sp += (double)sg;
            float p = fminf(fmaxf(sg, 1e-7f), CLIP_HI);
            float ag = (float)((word >> (j * 8)) & 0xFFu) + ((i == jg) ? 1.f : 0.f);
            float wgt = (ag == 1.f) ? PWc : 1.f;
            float bce = -(ag * logf(p) + (1.f - ag) * log1pf(-p));
            sw += (double)(wgt * bce);
        }
    }
    __syncthreads();
    double* red = (double*)zsm;
    red[tid] = sp; __syncthreads();
    for (int o = 128; o > 0; o >>= 1) {
        if (tid < o) red[tid] += red[tid + o];
        __syncthreads();
    }
    if (tid == 0) atomicAdd(&accP[blockIdx.x], red[0]);
    __syncthreads();
    red[tid] = sw; __syncthreads();
    for (int o = 128; o > 0; o >>= 1) {
        if (tid < o) red[tid] += red[tid + o];
        __syncthreads();
    }
    if (tid == 0) atomicAdd(&accW[blockIdx.x], red[0]);
}

__global__ void k_fin(const double* __restrict__ accP, const double* __restrict__ accW,
                      const double* __restrict__ accK, float* __restrict__ out) {
    double sp = 0.0, sw = 0.0, sk = 0.0;
    for (int i = 0; i < 96; i++) { sp += accP[i]; sw += accW[i]; }
    for (int i = 0; i < 64; i++) sk += accK[i];
    double norm = N2D / ((N2D - sp) * 2.0);
    out[BSZ * 100]     = (float)(sk / (double)NN);
    out[BSZ * 100 + 1] = (float)(norm * (sw / N2D));
}

// ---------------- host launch ------------------------------------------------
extern "C" void kernel_launch(void* const* d_in, const int* in_sizes, int n_in,
                              void* d_out, int out_size) {
    const float* user_feats = (const float*)d_in[0];
    const int*   gnf        = (const int*)  d_in[1];
    const int*   eidx       = (const int*)  d_in[2];
    const float* h0         = (const float*)d_in[4];
    const float* eps        = (const float*)d_in[5];
    const float* emb        = (const float*)d_in[6];
    const float* mw1 = (const float*)d_in[7],  *mb1 = (const float*)d_in[8];
    const float* mw2 = (const float*)d_in[9],  *mb2 = (const float*)d_in[10];
    const float* wih0 = (const float*)d_in[11], *whh0 = (const float*)d_in[12];
    const float* bih0 = (const float*)d_in[13], *bhh0 = (const float*)d_in[14];
    const float* wih1 = (const float*)d_in[15], *whh1 = (const float*)d_in[16];
    const float* bih1 = (const float*)d_in[17], *bhh1 = (const float*)d_in[18];
    const float* c1w = (const float*)d_in[19], *c1b = (const float*)d_in[20];
    const float* cmw = (const float*)d_in[21], *cmb = (const float*)d_in[22];
    const float* clw = (const float*)d_in[23], *clb = (const float*)d_in[24];
    float* out = (float*)d_out;
    const int* srcp = eidx;
    const int* dstp = eidx + NEDGE;

    void* p;
    cudaGetSymbolAddress(&p, g_Gi);  float* Gi  = (float*)p;
    cudaGetSymbolAddress(&p, g_Y0);  float* Y0  = (float*)p;
    cudaGetSymbolAddress(&p, g_T1);  float* T1  = (float*)p;
    cudaGetSymbolAddress(&p, g_Xin); float* Xin = (float*)p;
    cudaGetSymbolAddress(&p, g_XW);  float* XW  = (float*)p;
    cudaGetSymbolAddress(&p, g_Hc);  float* Hc  = (float*)p;
    cudaGetSymbolAddress(&p, g_MU);  float* MU  = (float*)p;
    cudaGetSymbolAddress(&p, g_LV);  float* LV  = (float*)p;
    cudaGetSymbolAddress(&p, g_Z);   float* Z   = (float*)p;
    cudaGetSymbolAddress(&p, g_deg); float* deg = (float*)p;
    cudaGetSymbolAddress(&p, g_dis); float* dis = (float*)p;
    cudaGetSymbolAddress(&p, g_Acnt);   unsigned* Acnt = (unsigned*)p;
    cudaGetSymbolAddress(&p, g_accP);   double* accP = (double*)p;
    cudaGetSymbolAddress(&p, g_accW);   double* accW = (double*)p;
    cudaGetSymbolAddress(&p, g_accK);   double* accK = (double*)p;

    cudaFuncSetAttribute(gru_persist<0>, cudaFuncAttributeMaxDynamicSharedMemorySize, GRU_SMEM);
    cudaFuncSetAttribute(gru_persist<1>, cudaFuncAttributeMaxDynamicSharedMemorySize, GRU_SMEM);
    cudaFuncSetAttribute(k_zzt2, cudaFuncAttributeMaxDynamicSharedMemorySize, ZZT_SMEM);

    // zero scratch
    cudaMemsetAsync(Acnt, 0, (size_t)NN * (NN/4) * sizeof(unsigned));
    cudaMemsetAsync(deg, 0, NN * sizeof(float));
    cudaMemsetAsync(accP, 0, 96 * sizeof(double));
    cudaMemsetAsync(accW, 0, 96 * sizeof(double));
    cudaMemsetAsync(accK, 0, 64 * sizeof(double));

    // graph structure
    k_scatter_cnt<<<(NEDGE + 255)/256, 256>>>(srcp, dstp, Acnt, deg);
    k_dis<<<(NN + 255)/256, 256>>>(deg, dis);

    // E2G = emb @ wih0^T + bih0  (vocab-side precompute, 4.5 GMAC)
    sgemm<<<dim3(5, (VOCAB + BM - 1)/BM), 256>>>(emb, wih0, bih0, Gi, VOCAB, 300, 300, 1, 0);

    // user encoder MLP -> straight into Xin rows [2048, 4096)
    sgemm<<<dim3(2, 16), 256>>>(user_feats, mw1, mb1, T1, NUSR, 100, 9, 0, 1);
    sgemm<<<dim3(2, 16), 256>>>(T1, mw2, mb2, Xin + (size_t)BSZ*100, NUSR, 100, 100, 0, 0);

    // GRU layer 0 (persistent, gathers gi from E2G via tokens)
    gru_persist<0><<<128, 256, GRU_SMEM>>>(Gi, gnf, whh0, bhh0, h0, Y0);

    // hoisted layer-1 input gates: Y0 @ wih1^T + bih1 (overwrites E2G region)
    sgemm<<<dim3(5, RALL/BM), 256>>>(Y0, wih1, bih1, Gi, RALL, 300, 100, 1, 0);

    // GRU layer 1 (persistent, writes final h scattered into Xin)
    gru_persist<1><<<128, 256, GRU_SMEM>>>(Gi, nullptr, whh1, bhh1,
                                           h0 + (size_t)NTW*HID, Xin);

    // conv1 -> elu
    sgemm<<<dim3(1, 48), 256>>>(Xin, c1w, nullptr, XW, NN, 64, 100, 0, 0);
    k_ginit<<<(NN*64 + 255)/256, 256>>>(XW, dis, c1b, Hc, 64);
    k_gscat<<<(NEDGE*64 + 255)/256, 256>>>(XW, srcp, dstp, dis, Hc, 64);
    k_act<<<(NN*64 + 255)/256, 256>>>(Hc, NN*64, 0);

    // convmu -> relu
    sgemm<<<dim3(2, 48), 256>>>(Hc, cmw, nullptr, XW, NN, 100, 64, 0, 0);
    k_ginit<<<(NN*100 + 255)/256, 256>>>(XW, dis, cmb, MU, 100);
    k_gscat<<<(NEDGE*100 + 255)/256, 256>>>(XW, srcp, dstp, dis, MU, 100);
    k_act<<<(NN*100 + 255)/256, 256>>>(MU, NN*100, 1);

    // convlv -> relu
    sgemm<<<dim3(2, 48), 256>>>(Hc, clw, nullptr, XW, NN, 100, 64, 0, 0);
    k_ginit<<<(NN*100 + 255)/256, 256>>>(XW, dis, clb, LV, 100);
    k_gscat<<<(NEDGE*100 + 255)/256, 256>>>(XW, srcp, dstp, dis, LV, 100);
    k_act<<<(NN*100 + 255)/256, 256>>>(LV, NN*100, 1);

    // reparametrize (+ copy Z[:bs] to out), KL, ZZ^T loss, finalize
    k_rep<<<(NN*100 + 255)/256, 256>>>(MU, LV, eps, Z, out);
    k_kl<<<512, 256>>>(MU, LV, accK);
    k_zzt2<<<dim3(96, 96), 256, ZZT_SMEM>>>(Z, Acnt, accP, accW);
    k_fin<<<1, 1>>>(accP, accW, accK, out);
}

// round 5
// speedup vs baseline: 2.5019x; 1.6851x over previous
#include <cuda_runtime.h>
#include <math.h>
#include <stdint.h>

#define NTW   4096
#define NUSR  2048
#define NN    6144
#define NEDGE 98304
#define SEQL  32
#define EMB   300
#define HID   100
#define BSZ   2048
#define VOCAB 50000
#define RALL  (NTW*SEQL)          /* 131072 */
#define N2D   37748736.0          /* NN*NN */
#define PWc   ((float)((37748736.0-104448.0)/104448.0))

// ---------------- scratch ---------------------------------------------------
__device__ float    g_Gi [(size_t)RALL*300];   // E2G (60MB) then Gi1 (157MB)
__device__ float    g_Y0 [(size_t)RALL*HID];   // layer-0 outputs (52MB)
__device__ float    g_T1 [NUSR*100];
__device__ float    g_Xin[NN*100];
__device__ float    g_XW [NN*100];
__device__ float    g_Hc [NN*64];
__device__ float    g_MU [NN*100];
__device__ float    g_LV [NN*100];
__device__ float    g_Z  [NN*100];
__device__ float    g_deg[NN];
__device__ float    g_dis[NN];
__device__ unsigned g_Acnt[(size_t)NN*(NN/4)]; // packed u8 counts, 37.7MB
__device__ double   g_accP[96];
__device__ double   g_accW[96];
__device__ double   g_accK[64];

// ---------------- SGEMM v2: vectorized loads + register-staged prefetch -----
#define BM 128
#define BN 64
#define BK 16

template<int BT>
__global__ __launch_bounds__(256) void sgemm2(
    const float* __restrict__ A, const float* __restrict__ B,
    const float* __restrict__ bias, float* __restrict__ C,
    int M, int N, int K, int act)
{
    __shared__ __align__(16) float As[BK][BM+4];
    __shared__ __align__(16) float Bs[BK][BN+4];
    int tid = threadIdx.x;
    int m0 = blockIdx.y * BM, n0 = blockIdx.x * BN;

    // A loader: row ra, 8 k's starting at ka
    int ra = tid >> 1, ka = (tid & 1) * 8;
    int gmA = m0 + ra;
    bool rokA = gmA < M;
    const float* Arow = A + (size_t)(rokA ? gmA : 0) * K;
    const bool kal = ((K & 3) == 0);

    // B loader indices
    int rb, kb;
    if (BT) { rb = tid >> 2; kb = (tid & 3) * 4; }     // B[N][K]: row rb, 4 k's
    else    { rb = tid >> 4; kb = (tid & 15) * 4; }    // B[K][N]: k-row rb, 4 cols
    const float* Brow = BT ? (B + (size_t)((n0 + rb) < N ? (n0 + rb) : 0) * K) : B;
    bool rokB = BT ? ((n0 + rb) < N) : true;

    float4 rA0, rA1, rB;

    auto fetch = [&](int k0) {
        rA0 = make_float4(0.f,0.f,0.f,0.f);
        rA1 = make_float4(0.f,0.f,0.f,0.f);
        if (rokA) {
            int k = k0 + ka;
            if (kal && (k + 7) < K) {
                rA0 = *(const float4*)(Arow + k);
                rA1 = *(const float4*)(Arow + k + 4);
            } else {
                float t[8];
                #pragma unroll
                for (int i = 0; i < 8; i++) t[i] = ((k+i) < K) ? Arow[k+i] : 0.f;
                rA0 = make_float4(t[0],t[1],t[2],t[3]);
                rA1 = make_float4(t[4],t[5],t[6],t[7]);
            }
        }
        rB = make_float4(0.f,0.f,0.f,0.f);
        if (BT) {
            if (rokB) {
                int k = k0 + kb;
                if (kal && (k + 3) < K) {
                    rB = *(const float4*)(Brow + k);
                } else {
                    float t[4];
                    #pragma unroll
                    for (int i = 0; i < 4; i++) t[i] = ((k+i) < K) ? Brow[k+i] : 0.f;
                    rB = make_float4(t[0],t[1],t[2],t[3]);
                }
            }
        } else {
            int kk = k0 + rb;
            if (kk < K) {
                float t[4];
                #pragma unroll
                for (int i = 0; i < 4; i++) {
                    int col = n0 + kb + i;
                    t[i] = (col < N) ? B[(size_t)kk * N + col] : 0.f;
                }
                rB = make_float4(t[0],t[1],t[2],t[3]);
            }
        }
    };
    auto stage = [&]() {
        As[ka+0][ra] = rA0.x; As[ka+1][ra] = rA0.y;
        As[ka+2][ra] = rA0.z; As[ka+3][ra] = rA0.w;
        As[ka+4][ra] = rA1.x; As[ka+5][ra] = rA1.y;
        As[ka+6][ra] = rA1.z; As[ka+7][ra] = rA1.w;
        if (BT) {
            Bs[kb+0][rb] = rB.x; Bs[kb+1][rb] = rB.y;
            Bs[kb+2][rb] = rB.z; Bs[kb+3][rb] = rB.w;
        } else {
            Bs[rb][kb+0] = rB.x; Bs[rb][kb+1] = rB.y;
            Bs[rb][kb+2] = rB.z; Bs[rb][kb+3] = rB.w;
        }
    };

    float acc[8][4];
    #pragma unroll
    for (int i = 0; i < 8; i++)
        #pragma unroll
        for (int j = 0; j < 4; j++) acc[i][j] = 0.f;

    int ty = tid >> 4, tx = tid & 15;
    int T = (K + BK - 1) / BK;
    fetch(0);
    for (int t = 0; t < T; t++) {
        stage();
        __syncthreads();
        if (t + 1 < T) fetch((t + 1) * BK);
        #pragma unroll
        for (int k = 0; k < BK; k++) {
            float4 a0 = *(const float4*)&As[k][ty*8];
            float4 a1 = *(const float4*)&As[k][ty*8+4];
            float4 b0 = *(const float4*)&Bs[k][tx*4];
            float av[8] = {a0.x,a0.y,a0.z,a0.w,a1.x,a1.y,a1.z,a1.w};
            float bv[4] = {b0.x,b0.y,b0.z,b0.w};
            #pragma unroll
            for (int i = 0; i < 8; i++)
                #pragma unroll
                for (int j = 0; j < 4; j++)
                    acc[i][j] += av[i] * bv[j];
        }
        __syncthreads();
    }
    #pragma unroll
    for (int i = 0; i < 8; i++) {
        int m = m0 + ty*8 + i;
        if (m < M) {
            #pragma unroll
            for (int j = 0; j < 4; j++) {
                int n = n0 + tx*4 + j;
                if (n < N) {
                    float v = acc[i][j];
                    if (bias) v += bias[n];
                    if (act == 1) v = fmaxf(v, 0.f);
                    C[(size_t)m * N + n] = v;
                }
            }
        }
    }
}

// ---------------- persistent GRU layer --------------------------------------
// 128 blocks x 256 threads; block owns 32 rows for all 32 steps.
// smem: sW[100][320], sG[32][320], sH[32][104], sB[320], sTok[32][32]
#define GRU_SMEM 187648

template<int LAYER>
__global__ __launch_bounds__(256) void gru_persist(
    const float* __restrict__ GIsrc,
    const int*   __restrict__ gnf,
    const float* __restrict__ whh, const float* __restrict__ bhh,
    const float* __restrict__ h0,
    float* __restrict__ Yout)
{
    extern __shared__ float sm[];
    float* sW = sm;                    // 32000
    float* sG = sm + 32000;            // 10240
    float* sH = sm + 42240;            // 3328
    float* sB = sm + 45568;            // 320
    int*   sTok = (int*)(sm + 45888);  // 1024
    int tid = threadIdx.x;
    int rowbase = blockIdx.x * 32;

    for (int idx = tid; idx < 30000; idx += 256) {
        int c = idx / 100, k = idx - c * 100;
        sW[k*320 + c] = whh[idx];
    }
    for (int idx = tid; idx < 2000; idx += 256) {
        int k = idx / 20, c = 300 + (idx - (idx/20)*20);
        sW[k*320 + c] = 0.f;
    }
    for (int idx = tid; idx < 320; idx += 256) sB[idx] = (idx < 300) ? bhh[idx] : 0.f;
    for (int idx = tid; idx < 3200; idx += 256) {
        int r = idx / 100, c = idx - r * 100;
        sH[r*104 + c] = h0[(size_t)(rowbase + r)*100 + c];
    }
    if (LAYER == 0) {
        for (int idx = tid; idx < 1024; idx += 256)
            sTok[idx] = gnf[rowbase * SEQL + idx];
    }
    __syncthreads();

    // precompute gate-cell mapping (step-invariant)
    int pr[13], pc[13];
    #pragma unroll
    for (int q = 0; q < 13; q++) {
        int cell = tid + q * 256;
        pr[q] = cell / 100;
        pc[q] = cell - pr[q] * 100;
    }

    int r0 = (tid >> 6) * 8;
    int c0 = (tid & 63) * 5;

    for (int s = 0; s < SEQL; s++) {
        // ---- prefetch gi for this step (hidden behind the GEMM below) ----
        float pg[13][3];
        #pragma unroll
        for (int q = 0; q < 13; q++) {
            int cell = tid + q * 256;
            if (cell < 3200) {
                int r = pr[q], c = pc[q];
                const float* gi;
                if (LAYER == 0) {
                    int tok = sTok[r * SEQL + s];
                    gi = GIsrc + (size_t)tok * 300;
                } else {
                    gi = GIsrc + ((size_t)s * NTW + (rowbase + r)) * 300;
                }
                pg[q][0] = gi[c];
                pg[q][1] = gi[c + 100];
                pg[q][2] = gi[c + 200];
            }
        }

        // ---- GH = sH @ sW (32x100 @ 100x320) ----
        float acc[8][5];
        #pragma unroll
        for (int e = 0; e < 8; e++)
            #pragma unroll
            for (int j = 0; j < 5; j++) acc[e][j] = 0.f;

        #pragma unroll 2
        for (int k = 0; k < 100; k++) {
            float hv[8];
            #pragma unroll
            for (int e = 0; e < 8; e++) hv[e] = sH[(r0+e)*104 + k];
            float w[5];
            #pragma unroll
            for (int j = 0; j < 5; j++) w[j] = sW[k*320 + c0 + j];
            #pragma unroll
            for (int e = 0; e < 8; e++)
                #pragma unroll
                for (int j = 0; j < 5; j++) acc[e][j] += hv[e] * w[j];
        }
        #pragma unroll
        for (int e = 0; e < 8; e++)
            #pragma unroll
            for (int j = 0; j < 5; j++) sG[(r0+e)*320 + c0 + j] = acc[e][j];
        __syncthreads();

        // ---- gate ----
        #pragma unroll
        for (int q = 0; q < 13; q++) {
            int cell = tid + q * 256;
            if (cell < 3200) {
                int r = pr[q], c = pc[q];
                float hr  = sG[r*320 + c]       + sB[c];
                float hz  = sG[r*320 + c + 100] + sB[c+100];
                float hnn = sG[r*320 + c + 200] + sB[c+200];
                float h   = sH[r*104 + c];
                float rg = 1.f / (1.f + expf(-(pg[q][0] + hr)));
                float zg = 1.f / (1.f + expf(-(pg[q][1] + hz)));
                float ng = tanhf(pg[q][2] + rg * hnn);
                float hn = (1.f - zg) * ng + zg * h;
                sH[r*104 + c] = hn;
                if (LAYER == 0)
                    Yout[((size_t)s * NTW + (rowbase + r)) * 100 + c] = hn;
            }
        }
        __syncthreads();
    }
    if (LAYER == 1) {
        for (int ii = tid; ii < 3200; ii += 256) {
            int r = ii / 100, c = ii - r * 100;
            int grow = rowbase + r;
            int orow = (grow < BSZ) ? grow : grow + NUSR;
            Yout[(size_t)orow * 100 + c] = sH[r*104 + c];
        }
    }
}

// ---------------- small kernels ----------------------------------------------
__global__ void k_scatter_cnt(const int* __restrict__ src, const int* __restrict__ dst,
                              unsigned* __restrict__ cnt, float* __restrict__ deg) {
    int e = blockIdx.x * 256 + threadIdx.x;
    if (e >= NEDGE) return;
    int s = src[e], d = dst[e];
    size_t idx = (size_t)s * NN + d;
    atomicAdd(&cnt[idx >> 2], 1u << ((idx & 3) * 8));
    atomicAdd(&deg[d], 1.f);
}
__global__ void k_dis(const float* __restrict__ deg, float* __restrict__ dis) {
    int i = blockIdx.x * 256 + threadIdx.x;
    if (i < NN) dis[i] = rsqrtf(deg[i] + 1.f);
}
__global__ void k_ginit(const float* __restrict__ xw, const float* __restrict__ dis,
                        const float* __restrict__ b, float* __restrict__ agg, int C) {
    int i = blockIdx.x * 256 + threadIdx.x;
    if (i >= NN * C) return;
    int n = i / C, c = i - n * C;
    float d = dis[n];
    agg[i] = xw[i] * d * d + b[c];
}
__global__ void k_gscat(const float* __restrict__ xw, const int* __restrict__ src,
                        const int* __restrict__ dst, const float* __restrict__ dis,
                        float* __restrict__ agg, int C) {
    int i = blockIdx.x * 256 + threadIdx.x;
    if (i >= NEDGE * C) return;
    int e = i / C, c = i - e * C;
    int s = src[e], d = dst[e];
    atomicAdd(&agg[(size_t)d * C + c], xw[(size_t)s * C + c] * dis[s] * dis[d]);
}
__global__ void k_act(float* __restrict__ x, int n, int mode) {
    int i = blockIdx.x * 256 + threadIdx.x;
    if (i >= n) return;
    float v = x[i];
    x[i] = mode ? fmaxf(v, 0.f) : (v > 0.f ? v : expm1f(v));
}
__global__ void k_rep(const float* __restrict__ MU, const float* __restrict__ LV,
                      const float* __restrict__ eps, float* __restrict__ Z,
                      float* __restrict__ out) {
    int i = blockIdx.x * 256 + threadIdx.x;
    if (i >= NN * 100) return;
    float z = MU[i] + expf(LV[i] * 0.5f) * eps[i];
    Z[i] = z;
    if (i < BSZ * 100) out[i] = z;
}
__global__ void k_kl(const float* __restrict__ MU, const float* __restrict__ LV,
                     double* __restrict__ accK) {
    __shared__ double red[256];
    double v = 0.0;
    for (int i = blockIdx.x * 256 + threadIdx.x; i < NN * 100; i += 512 * 256) {
        float mu = MU[i], lv = LV[i];
        v += (double)(-0.5f * (1.f + lv - mu * mu - expf(lv)));
    }
    red[threadIdx.x] = v; __syncthreads();
    for (int o = 128; o > 0; o >>= 1) {
        if (threadIdx.x < o) red[threadIdx.x] += red[threadIdx.x + o];
        __syncthreads();
    }
    if (threadIdx.x == 0) atomicAdd(&accK[blockIdx.x & 63], red[0]);
}

// ---------------- Z@Z^T loss: symmetric tiles + softplus BCE -----------------
#define ZZT_SMEM 51200
__global__ __launch_bounds__(256) void k_zzt3(const float* __restrict__ Z,
                                              const unsigned* __restrict__ cnt,
                                              double* __restrict__ accP,
                                              double* __restrict__ accW) {
    int biB = blockIdx.y, bjB = blockIdx.x;
    if (bjB < biB) return;                 // upper-triangular tile pairs only
    extern __shared__ float zsm[];
    float* Zi  = zsm;          // [64][100]
    float* ZjT = zsm + 6400;   // [100][64]
    int tid = threadIdx.x;
    int bi = biB * 64, bj = bjB * 64;

    for (int f = tid; f < 6400; f += 256) {
        int r = f / 100, c = f - r * 100;
        Zi[f] = Z[(size_t)(bi + r) * 100 + c];
    }
    for (int f = tid; f < 6400; f += 256) {
        int k = f >> 6, j = f & 63;
        ZjT[f] = Z[(size_t)(bj + j) * 100 + k];
    }
    __syncthreads();

    int ty = tid >> 4, tx = tid & 15;
    int i0 = ty * 4, j0 = tx * 4;
    float acc[4][4];
    #pragma unroll
    for (int e = 0; e < 4; e++)
        #pragma unroll
        for (int j = 0; j < 4; j++) acc[e][j] = 0.f;

    #pragma unroll 4
    for (int k = 0; k < 100; k++) {
        float4 b = *(const float4*)&ZjT[k * 64 + j0];
        float a0 = Zi[(i0+0)*100 + k];
        float a1 = Zi[(i0+1)*100 + k];
        float a2 = Zi[(i0+2)*100 + k];
        float a3 = Zi[(i0+3)*100 + k];
        acc[0][0]+=a0*b.x; acc[0][1]+=a0*b.y; acc[0][2]+=a0*b.z; acc[0][3]+=a0*b.w;
        acc[1][0]+=a1*b.x; acc[1][1]+=a1*b.y; acc[1][2]+=a1*b.z; acc[1][3]+=a1*b.w;
        acc[2][0]+=a2*b.x; acc[2][1]+=a2*b.y; acc[2][2]+=a2*b.z; acc[2][3]+=a2*b.w;
        acc[3][0]+=a3*b.x; acc[3][1]+=a3*b.y; acc[3][2]+=a3*b.z; acc[3][3]+=a3*b.w;
    }

    bool diag = (biB == bjB);
    // transposed-cell count words: row jg, column-word (bi>>2)+ty (const over e)
    unsigned w2j[4];
    if (!diag) {
        #pragma unroll
        for (int j = 0; j < 4; j++)
            w2j[j] = cnt[(size_t)(bj + j0 + j) * (NN/4) + (bi >> 2) + ty];
    }

    double sp = 0.0, sw = 0.0;
    #pragma unroll
    for (int e = 0; e < 4; e++) {
        int i = bi + i0 + e;
        unsigned w1 = cnt[(size_t)i * (NN/4) + (bj >> 2) + tx];
        #pragma unroll
        for (int j = 0; j < 4; j++) {
            int jg = bj + j0 + j;
            float z = acc[e][j];
            float ex = expf(-z);
            float s = 1.f / (1.f + ex);
            float logp, log1mp;
            if (z > 15.942384f) {            // s clipped to 1-2^-23
                logp = -1.1920929e-7f; log1mp = -15.9423847f;
            } else if (z < -16.118095f) {    // s clipped to 1e-7
                logp = -16.118095f;    log1mp = -1.0000000e-7f;
            } else {
                float spv = log1pf(ex);      // softplus(-z)
                logp = -spv; log1mp = -z - spv;
            }
            float ag1 = (float)((w1 >> (j*8)) & 0xFFu) + ((i == jg) ? 1.f : 0.f);
            float wg1 = (ag1 == 1.f) ? PWc : 1.f;
            sp += (double)s;
            sw += (double)(wg1 * (-(ag1 * logp + (1.f - ag1) * log1mp)));
            if (!diag) {
                float ag2 = (float)((w2j[j] >> (e*8)) & 0xFFu);  // (i&3)==e
                float wg2 = (ag2 == 1.f) ? PWc : 1.f;
                sp += (double)s;
                sw += (double)(wg2 * (-(ag2 * logp + (1.f - ag2) * log1mp)));
            }
        }
    }
    __syncthreads();
    double* red = (double*)zsm;
    red[tid] = sp; __syncthreads();
    for (int o = 128; o > 0; o >>= 1) {
        if (tid < o) red[tid] += red[tid + o];
        __syncthreads();
    }
    if (tid == 0) atomicAdd(&accP[bjB], red[0]);
    __syncthreads();
    red[tid] = sw; __syncthreads();
    for (int o = 128; o > 0; o >>= 1) {
        if (tid < o) red[tid] += red[tid + o];
        __syncthreads();
    }
    if (tid == 0) atomicAdd(&accW[bjB], red[0]);
}

__global__ void k_fin(const double* __restrict__ accP, const double* __restrict__ accW,
                      const double* __restrict__ accK, float* __restrict__ out) {
    double sp = 0.0, sw = 0.0, sk = 0.0;
    for (int i = 0; i < 96; i++) { sp += accP[i]; sw += accW[i]; }
    for (int i = 0; i < 64; i++) sk += accK[i];
    double norm = N2D / ((N2D - sp) * 2.0);
    out[BSZ * 100]     = (float)(sk / (double)NN);
    out[BSZ * 100 + 1] = (float)(norm * (sw / N2D));
}

// ---------------- host launch ------------------------------------------------
extern "C" void kernel_launch(void* const* d_in, const int* in_sizes, int n_in,
                              void* d_out, int out_size) {
    const float* user_feats = (const float*)d_in[0];
    const int*   gnf        = (const int*)  d_in[1];
    const int*   eidx       = (const int*)  d_in[2];
    const float* h0         = (const float*)d_in[4];
    const float* eps        = (const float*)d_in[5];
    const float* emb        = (const float*)d_in[6];
    const float* mw1 = (const float*)d_in[7],  *mb1 = (const float*)d_in[8];
    const float* mw2 = (const float*)d_in[9],  *mb2 = (const float*)d_in[10];
    const float* wih0 = (const float*)d_in[11], *whh0 = (const float*)d_in[12];
    const float* bih0 = (const float*)d_in[13], *bhh0 = (const float*)d_in[14];
    const float* wih1 = (const float*)d_in[15], *whh1 = (const float*)d_in[16];
    const float* bih1 = (const float*)d_in[17], *bhh1 = (const float*)d_in[18];
    const float* c1w = (const float*)d_in[19], *c1b = (const float*)d_in[20];
    const float* cmw = (const float*)d_in[21], *cmb = (const float*)d_in[22];
    const float* clw = (const float*)d_in[23], *clb = (const float*)d_in[24];
    float* out = (float*)d_out;
    const int* srcp = eidx;
    const int* dstp = eidx + NEDGE;

    void* p;
    cudaGetSymbolAddress(&p, g_Gi);  float* Gi  = (float*)p;
    cudaGetSymbolAddress(&p, g_Y0);  float* Y0  = (float*)p;
    cudaGetSymbolAddress(&p, g_T1);  float* T1  = (float*)p;
    cudaGetSymbolAddress(&p, g_Xin); float* Xin = (float*)p;
    cudaGetSymbolAddress(&p, g_XW);  float* XW  = (float*)p;
    cudaGetSymbolAddress(&p, g_Hc);  float* Hc  = (float*)p;
    cudaGetSymbolAddress(&p, g_MU);  float* MU  = (float*)p;
    cudaGetSymbolAddress(&p, g_LV);  float* LV  = (float*)p;
    cudaGetSymbolAddress(&p, g_Z);   float* Z   = (float*)p;
    cudaGetSymbolAddress(&p, g_deg); float* deg = (float*)p;
    cudaGetSymbolAddress(&p, g_dis); float* dis = (float*)p;
    cudaGetSymbolAddress(&p, g_Acnt);   unsigned* Acnt = (unsigned*)p;
    cudaGetSymbolAddress(&p, g_accP);   double* accP = (double*)p;
    cudaGetSymbolAddress(&p, g_accW);   double* accW = (double*)p;
    cudaGetSymbolAddress(&p, g_accK);   double* accK = (double*)p;

    cudaFuncSetAttribute(gru_persist<0>, cudaFuncAttributeMaxDynamicSharedMemorySize, GRU_SMEM);
    cudaFuncSetAttribute(gru_persist<1>, cudaFuncAttributeMaxDynamicSharedMemorySize, GRU_SMEM);
    cudaFuncSetAttribute(k_zzt3, cudaFuncAttributeMaxDynamicSharedMemorySize, ZZT_SMEM);

    cudaMemsetAsync(Acnt, 0, (size_t)NN * (NN/4) * sizeof(unsigned));
    cudaMemsetAsync(deg, 0, NN * sizeof(float));
    cudaMemsetAsync(accP, 0, 96 * sizeof(double));
    cudaMemsetAsync(accW, 0, 96 * sizeof(double));
    cudaMemsetAsync(accK, 0, 64 * sizeof(double));

    k_scatter_cnt<<<(NEDGE + 255)/256, 256>>>(srcp, dstp, Acnt, deg);
    k_dis<<<(NN + 255)/256, 256>>>(deg, dis);

    // user encoder MLP -> Xin rows [2048, 4096)
    sgemm2<0><<<dim3(2, 16), 256>>>(user_feats, mw1, mb1, T1, NUSR, 100, 9, 1);
    sgemm2<0><<<dim3(2, 16), 256>>>(T1, mw2, mb2, Xin + (size_t)BSZ*100, NUSR, 100, 100, 0);

    // E2G = emb @ wih0^T + bih0 (vocab-side precompute)
    sgemm2<1><<<dim3(5, (VOCAB + BM - 1)/BM), 256>>>(emb, wih0, bih0, Gi, VOCAB, 300, 300, 0);

    // GRU layer 0
    gru_persist<0><<<128, 256, GRU_SMEM>>>(Gi, gnf, whh0, bhh0, h0, Y0);

    // layer-1 input gates: Y0 @ wih1^T + bih1
    sgemm2<1><<<dim3(5, RALL/BM), 256>>>(Y0, wih1, bih1, Gi, RALL, 300, 100, 0);

    // GRU layer 1 (writes final h scattered into Xin)
    gru_persist<1><<<128, 256, GRU_SMEM>>>(Gi, nullptr, whh1, bhh1,
                                           h0 + (size_t)NTW*HID, Xin);

    // conv1 -> elu
    sgemm2<0><<<dim3(1, 48), 256>>>(Xin, c1w, nullptr, XW, NN, 64, 100, 0);
    k_ginit<<<(NN*64 + 255)/256, 256>>>(XW, dis, c1b, Hc, 64);
    k_gscat<<<(NEDGE*64 + 255)/256, 256>>>(XW, srcp, dstp, dis, Hc, 64);
    k_act<<<(NN*64 + 255)/256, 256>>>(Hc, NN*64, 0);

    // convmu -> relu
    sgemm2<0><<<dim3(2, 48), 256>>>(Hc, cmw, nullptr, XW, NN, 100, 64, 0);
    k_ginit<<<(NN*100 + 255)/256, 256>>>(XW, dis, cmb, MU, 100);
    k_gscat<<<(NEDGE*100 + 255)/256, 256>>>(XW, srcp, dstp, dis, MU, 100);
    k_act<<<(NN*100 + 255)/256, 256>>>(MU, NN*100, 1);

    // convlv -> relu
    sgemm2<0><<<dim3(2, 48), 256>>>(Hc, clw, nullptr, XW, NN, 100, 64, 0);
    k_ginit<<<(NN*100 + 255)/256, 256>>>(XW, dis, clb, LV, 100);
    k_gscat<<<(NEDGE*100 + 255)/256, 256>>>(XW, srcp, dstp, dis, LV, 100);
    k_act<<<(NN*100 + 255)/256, 256>>>(LV, NN*100, 1);

    k_rep<<<(NN*100 + 255)/256, 256>>>(MU, LV, eps, Z, out);
    k_kl<<<512, 256>>>(MU, LV, accK);
    k_zzt3<<<dim3(96, 96), 256, ZZT_SMEM>>>(Z, Acnt, accP, accW);
    k_fin<<<1, 1>>>(accP, accW, accK, out);
}

// round 6
// speedup vs baseline: 2.6747x; 1.0691x over previous
#include <cuda_runtime.h>
#include <math.h>
#include <stdint.h>

typedef unsigned long long u64;

#define NTW   4096
#define NUSR  2048
#define NN    6144
#define NEDGE 98304
#define SEQL  32
#define EMB   300
#define HID   100
#define BSZ   2048
#define VOCAB 50000
#define RALL  (NTW*SEQL)          /* 131072 */
#define N2D   37748736.0          /* NN*NN */
#define PWc   ((float)((37748736.0-104448.0)/104448.0))

// ---------------- f32x2 helpers ---------------------------------------------
__device__ __forceinline__ u64 bc2(float x) {
    u64 r; asm("mov.b64 %0, {%1, %1};" : "=l"(r) : "f"(x)); return r;
}
__device__ __forceinline__ void up2(u64 v, float& lo, float& hi) {
    asm("mov.b64 {%0, %1}, %2;" : "=f"(lo), "=f"(hi) : "l"(v));
}
__device__ __forceinline__ void fma2(u64& d, u64 a, u64 b) {
    asm("fma.rn.f32x2 %0, %1, %2, %0;" : "+l"(d) : "l"(a), "l"(b));
}

// ---------------- scratch ---------------------------------------------------
__device__ float    g_Gi [(size_t)RALL*300];
__device__ float    g_Y0 [(size_t)RALL*HID];
__device__ float    g_T1 [NUSR*100];
__device__ float    g_Xin[NN*100];
__device__ float    g_XW [NN*100];
__device__ float    g_Hc [NN*64];
__device__ float    g_MU [NN*100];
__device__ float    g_LV [NN*100];
__device__ float    g_Z  [NN*100];
__device__ float    g_deg[NN];
__device__ float    g_dis[NN];
__device__ unsigned g_Acnt[(size_t)NN*(NN/4)];
__device__ double   g_accP[96];
__device__ double   g_accW[96];
__device__ double   g_accK[64];

// ---------------- SGEMM v3: 128x128 tile, 8x8 micro, f32x2 ------------------
// C[M,N] = A[M,K] @ (BT? B[N,K]^T : B[K,N]).
// dis==null:  C = act(v + bias)
// dis!=null:  Craw = v ; C = v*dis[m]^2 + bias[n]   (GCN self-loop init fused)
template<int BT>
__global__ __launch_bounds__(256) void sgemm3(
    const float* __restrict__ A, const float* __restrict__ B,
    const float* __restrict__ bias, float* __restrict__ C,
    float* __restrict__ Craw, const float* __restrict__ dis,
    int M, int N, int K, int act)
{
    __shared__ __align__(16) float As[16][132];
    __shared__ __align__(16) float Bs[16][132];
    int tid = threadIdx.x;
    int m0 = blockIdx.y * 128, n0 = blockIdx.x * 128;

    int ra = tid >> 1, ka = (tid & 1) * 8;
    int gmA = m0 + ra;
    bool rokA = gmA < M;
    const float* Arow = A + (size_t)(rokA ? gmA : 0) * K;
    bool kal = ((K & 3) == 0);

    int rb, kb;
    const float* Brow = nullptr;
    bool rokB = true;
    if (BT) {
        rb = tid >> 1; kb = (tid & 1) * 8;
        rokB = (n0 + rb) < N;
        Brow = B + (size_t)(rokB ? (n0 + rb) : 0) * K;
    } else {
        rb = tid >> 4; kb = (tid & 15) * 8;
    }

    float4 rA0, rA1, rB0, rB1;

    auto fetch = [&](int k0) {
        rA0 = make_float4(0.f,0.f,0.f,0.f); rA1 = rA0;
        if (rokA) {
            int k = k0 + ka;
            if (kal && (k + 7) < K) {
                rA0 = *(const float4*)(Arow + k);
                rA1 = *(const float4*)(Arow + k + 4);
            } else {
                float t[8];
                #pragma unroll
                for (int i = 0; i < 8; i++) t[i] = ((k+i) < K) ? Arow[k+i] : 0.f;
                rA0 = make_float4(t[0],t[1],t[2],t[3]);
                rA1 = make_float4(t[4],t[5],t[6],t[7]);
            }
        }
        rB0 = make_float4(0.f,0.f,0.f,0.f); rB1 = rB0;
        if (BT) {
            if (rokB) {
                int k = k0 + kb;
                if (kal && (k + 7) < K) {
                    rB0 = *(const float4*)(Brow + k);
                    rB1 = *(const float4*)(Brow + k + 4);
                } else {
                    float t[8];
                    #pragma unroll
                    for (int i = 0; i < 8; i++) t[i] = ((k+i) < K) ? Brow[k+i] : 0.f;
                    rB0 = make_float4(t[0],t[1],t[2],t[3]);
                    rB1 = make_float4(t[4],t[5],t[6],t[7]);
                }
            }
        } else {
            int kk = k0 + rb;
            float t[8];
            #pragma unroll
            for (int i = 0; i < 8; i++) {
                int col = n0 + kb + i;
                t[i] = (kk < K && col < N) ? B[(size_t)kk * N + col] : 0.f;
            }
            rB0 = make_float4(t[0],t[1],t[2],t[3]);
            rB1 = make_float4(t[4],t[5],t[6],t[7]);
        }
    };
    auto stage = [&]() {
        As[ka+0][ra]=rA0.x; As[ka+1][ra]=rA0.y; As[ka+2][ra]=rA0.z; As[ka+3][ra]=rA0.w;
        As[ka+4][ra]=rA1.x; As[ka+5][ra]=rA1.y; As[ka+6][ra]=rA1.z; As[ka+7][ra]=rA1.w;
        if (BT) {
            Bs[kb+0][rb]=rB0.x; Bs[kb+1][rb]=rB0.y; Bs[kb+2][rb]=rB0.z; Bs[kb+3][rb]=rB0.w;
            Bs[kb+4][rb]=rB1.x; Bs[kb+5][rb]=rB1.y; Bs[kb+6][rb]=rB1.z; Bs[kb+7][rb]=rB1.w;
        } else {
            Bs[rb][kb+0]=rB0.x; Bs[rb][kb+1]=rB0.y; Bs[rb][kb+2]=rB0.z; Bs[rb][kb+3]=rB0.w;
            Bs[rb][kb+4]=rB1.x; Bs[rb][kb+5]=rB1.y; Bs[rb][kb+6]=rB1.z; Bs[rb][kb+7]=rB1.w;
        }
    };

    u64 acc[4][8];
    #pragma unroll
    for (int p = 0; p < 4; p++)
        #pragma unroll
        for (int q = 0; q < 8; q++) acc[p][q] = 0ull;

    int ty = tid >> 4, tx = tid & 15;
    int i0 = ty * 8;
    int T = (K + 15) / 16;
    fetch(0);
    for (int t = 0; t < T; t++) {
        stage();
        __syncthreads();
        if (t + 1 < T) fetch((t + 1) * 16);
        #pragma unroll
        for (int k = 0; k < 16; k++) {
            u64 a2[4];
            #pragma unroll
            for (int p = 0; p < 4; p++)
                a2[p] = *(const u64*)&As[k][i0 + 2*p];
            #pragma unroll
            for (int q = 0; q < 8; q++) {
                u64 bb = bc2(Bs[k][q*16 + tx]);
                #pragma unroll
                for (int p = 0; p < 4; p++) fma2(acc[p][q], a2[p], bb);
            }
        }
        __syncthreads();
    }

    #pragma unroll
    for (int p = 0; p < 4; p++) {
        int m1 = m0 + i0 + 2*p, m2 = m1 + 1;
        float d1 = 0.f, d2 = 0.f;
        if (dis) {
            if (m1 < M) { float d = dis[m1]; d1 = d*d; }
            if (m2 < M) { float d = dis[m2]; d2 = d*d; }
        }
        #pragma unroll
        for (int q = 0; q < 8; q++) {
            int n = n0 + q*16 + tx;
            if (n >= N) continue;
            float lo, hi; up2(acc[p][q], lo, hi);
            if (dis) {
                float bv = bias[n];
                if (m1 < M) { Craw[(size_t)m1*N+n] = lo; C[(size_t)m1*N+n] = lo*d1 + bv; }
                if (m2 < M) { Craw[(size_t)m2*N+n] = hi; C[(size_t)m2*N+n] = hi*d2 + bv; }
            } else {
                if (m1 < M) {
                    float v = lo; if (bias) v += bias[n];
                    if (act == 1) v = fmaxf(v, 0.f);
                    C[(size_t)m1*N+n] = v;
                }
                if (m2 < M) {
                    float v = hi; if (bias) v += bias[n];
                    if (act == 1) v = fmaxf(v, 0.f);
                    C[(size_t)m2*N+n] = v;
                }
            }
        }
    }
}

// ---------------- persistent GRU layer (f32x2 + transposed H) ---------------
// smem: sW[100][320], sG[32][320], sHT[100][34], sB[320], sTok[32*32]
#define GRU_SMEM 187936

template<int LAYER>
__global__ __launch_bounds__(256) void gru_persist(
    const float* __restrict__ GIsrc,
    const int*   __restrict__ gnf,
    const float* __restrict__ whh, const float* __restrict__ bhh,
    const float* __restrict__ h0,
    float* __restrict__ Yout)
{
    extern __shared__ float sm[];
    float* sW  = sm;                   // 32000
    float* sG  = sm + 32000;           // 10240
    float* sHT = sm + 42240;           // 3400
    float* sB  = sm + 45640;           // 320
    int*  sTok = (int*)(sm + 45960);   // 1024
    int tid = threadIdx.x;
    int rowbase = blockIdx.x * 32;

    for (int idx = tid; idx < 30000; idx += 256) {
        int c = idx / 100, k = idx - c * 100;
        sW[k*320 + c] = whh[idx];
    }
    for (int idx = tid; idx < 2000; idx += 256) {
        int k = idx / 20, c = 300 + (idx - (idx/20)*20);
        sW[k*320 + c] = 0.f;
    }
    for (int idx = tid; idx < 320; idx += 256) sB[idx] = (idx < 300) ? bhh[idx] : 0.f;
    for (int idx = tid; idx < 3200; idx += 256) {
        int r = idx / 100, c = idx - r * 100;
        sHT[c*34 + r] = h0[(size_t)(rowbase + r)*100 + c];
    }
    if (LAYER == 0) {
        for (int idx = tid; idx < 1024; idx += 256)
            sTok[idx] = gnf[rowbase * SEQL + idx];
    }
    __syncthreads();

    int pr[13], pc[13];
    #pragma unroll
    for (int q = 0; q < 13; q++) {
        int cell = tid + q * 256;
        pr[q] = cell / 100;
        pc[q] = cell - pr[q] * 100;
    }

    int r0 = (tid >> 6) * 8;
    int c0 = (tid & 63) * 5;

    for (int s = 0; s < SEQL; s++) {
        // prefetch gi (hidden behind GEMM)
        float pg[13][3];
        #pragma unroll
        for (int q = 0; q < 13; q++) {
            int cell = tid + q * 256;
            if (cell < 3200) {
                int r = pr[q], c = pc[q];
                const float* gi;
                if (LAYER == 0) {
                    int tok = sTok[r * SEQL + s];
                    gi = GIsrc + (size_t)tok * 300;
                } else {
                    gi = GIsrc + ((size_t)s * NTW + (rowbase + r)) * 300;
                }
                pg[q][0] = gi[c];
                pg[q][1] = gi[c + 100];
                pg[q][2] = gi[c + 200];
            }
        }

        // GH = H @ Whh^T : 32x100 @ 100x320, f32x2 row-pairs
        u64 acc[4][5];
        #pragma unroll
        for (int p = 0; p < 4; p++)
            #pragma unroll
            for (int j = 0; j < 5; j++) acc[p][j] = 0ull;

        #pragma unroll 2
        for (int k = 0; k < 100; k++) {
            u64 a2[4];
            #pragma unroll
            for (int p = 0; p < 4; p++)
                a2[p] = *(const u64*)&sHT[k*34 + r0 + 2*p];
            #pragma unroll
            for (int j = 0; j < 5; j++) {
                u64 bb = bc2(sW[k*320 + c0 + j]);
                #pragma unroll
                for (int p = 0; p < 4; p++) fma2(acc[p][j], a2[p], bb);
            }
        }
        #pragma unroll
        for (int p = 0; p < 4; p++)
            #pragma unroll
            for (int j = 0; j < 5; j++) {
                float lo, hi; up2(acc[p][j], lo, hi);
                sG[(r0 + 2*p    )*320 + c0 + j] = lo;
                sG[(r0 + 2*p + 1)*320 + c0 + j] = hi;
            }
        __syncthreads();

        // gates (fast math)
        #pragma unroll
        for (int q = 0; q < 13; q++) {
            int cell = tid + q * 256;
            if (cell < 3200) {
                int r = pr[q], c = pc[q];
                float hr  = sG[r*320 + c]       + sB[c];
                float hz  = sG[r*320 + c + 100] + sB[c+100];
                float hnn = sG[r*320 + c + 200] + sB[c+200];
                float h   = sHT[c*34 + r];
                float rg = __fdividef(1.f, 1.f + __expf(-(pg[q][0] + hr)));
                float zg = __fdividef(1.f, 1.f + __expf(-(pg[q][1] + hz)));
                float x  = pg[q][2] + rg * hnn;
                float t  = __expf(-2.f * fabsf(x));
                float ng = copysignf(__fdividef(1.f - t, 1.f + t), x);
                float hn = (1.f - zg) * ng + zg * h;
                sHT[c*34 + r] = hn;
                if (LAYER == 0)
                    Yout[((size_t)s * NTW + (rowbase + r)) * 100 + c] = hn;
            }
        }
        __syncthreads();
    }
    if (LAYER == 1) {
        for (int ii = tid; ii < 3200; ii += 256) {
            int r = ii / 100, c = ii - r * 100;
            int grow = rowbase + r;
            int orow = (grow < BSZ) ? grow : grow + NUSR;
            Yout[(size_t)orow * 100 + c] = sHT[c*34 + r];
        }
    }
}

// ---------------- small kernels ----------------------------------------------
__global__ void k_scatter_cnt(const int* __restrict__ src, const int* __restrict__ dst,
                              unsigned* __restrict__ cnt, float* __restrict__ deg) {
    int e = blockIdx.x * 256 + threadIdx.x;
    if (e >= NEDGE) return;
    int s = src[e], d = dst[e];
    size_t idx = (size_t)s * NN + d;
    atomicAdd(&cnt[idx >> 2], 1u << ((idx & 3) * 8));
    atomicAdd(&deg[d], 1.f);
}
__global__ void k_dis(const float* __restrict__ deg, float* __restrict__ dis) {
    int i = blockIdx.x * 256 + threadIdx.x;
    if (i < NN) dis[i] = rsqrtf(deg[i] + 1.f);
}
__global__ void k_gscat(const float* __restrict__ xw, const int* __restrict__ src,
                        const int* __restrict__ dst, const float* __restrict__ dis,
                        float* __restrict__ agg, int C) {
    int i = blockIdx.x * 256 + threadIdx.x;
    if (i >= NEDGE * C) return;
    int e = i / C, c = i - e * C;
    int s = src[e], d = dst[e];
    atomicAdd(&agg[(size_t)d * C + c], xw[(size_t)s * C + c] * dis[s] * dis[d]);
}
__global__ void k_act(float* __restrict__ x, int n, int mode) {
    int i = blockIdx.x * 256 + threadIdx.x;
    if (i >= n) return;
    float v = x[i];
    x[i] = mode ? fmaxf(v, 0.f) : (v > 0.f ? v : expm1f(v));
}
__global__ void k_rep(const float* __restrict__ MU, const float* __restrict__ LV,
                      const float* __restrict__ eps, float* __restrict__ Z,
                      float* __restrict__ out) {
    int i = blockIdx.x * 256 + threadIdx.x;
    if (i >= NN * 100) return;
    float z = MU[i] + expf(LV[i] * 0.5f) * eps[i];
    Z[i] = z;
    if (i < BSZ * 100) out[i] = z;
}
__global__ void k_kl(const float* __restrict__ MU, const float* __restrict__ LV,
                     double* __restrict__ accK) {
    __shared__ double red[256];
    double v = 0.0;
    for (int i = blockIdx.x * 256 + threadIdx.x; i < NN * 100; i += 512 * 256) {
        float mu = MU[i], lv = LV[i];
        v += (double)(-0.5f * (1.f + lv - mu * mu - expf(lv)));
    }
    red[threadIdx.x] = v; __syncthreads();
    for (int o = 128; o > 0; o >>= 1) {
        if (threadIdx.x < o) red[threadIdx.x] += red[threadIdx.x + o];
        __syncthreads();
    }
    if (threadIdx.x == 0) atomicAdd(&accK[blockIdx.x & 63], red[0]);
}

// ---------------- Z@Z^T loss: symmetric tiles + softplus BCE -----------------
#define ZZT_SMEM 51200
__global__ __launch_bounds__(256) void k_zzt3(const float* __restrict__ Z,
                                              const unsigned* __restrict__ cnt,
                                              double* __restrict__ accP,
                                              double* __restrict__ accW) {
    int biB = blockIdx.y, bjB = blockIdx.x;
    if (bjB < biB) return;
    extern __shared__ float zsm[];
    float* Zi  = zsm;          // [64][100]
    float* ZjT = zsm + 6400;   // [100][64]
    int tid = threadIdx.x;
    int bi = biB * 64, bj = bjB * 64;

    for (int f = tid; f < 6400; f += 256) {
        int r = f / 100, c = f - r * 100;
        Zi[f] = Z[(size_t)(bi + r) * 100 + c];
    }
    for (int f = tid; f < 6400; f += 256) {
        int k = f >> 6, j = f & 63;
        ZjT[f] = Z[(size_t)(bj + j) * 100 + k];
    }
    __syncthreads();

    int ty = tid >> 4, tx = tid & 15;
    int i0 = ty * 4, j0 = tx * 4;
    float acc[4][4];
    #pragma unroll
    for (int e = 0; e < 4; e++)
        #pragma unroll
        for (int j = 0; j < 4; j++) acc[e][j] = 0.f;

    #pragma unroll 4
    for (int k = 0; k < 100; k++) {
        float4 b = *(const float4*)&ZjT[k * 64 + j0];
        float a0 = Zi[(i0+0)*100 + k];
        float a1 = Zi[(i0+1)*100 + k];
        float a2 = Zi[(i0+2)*100 + k];
        float a3 = Zi[(i0+3)*100 + k];
        acc[0][0]+=a0*b.x; acc[0][1]+=a0*b.y; acc[0][2]+=a0*b.z; acc[0][3]+=a0*b.w;
        acc[1][0]+=a1*b.x; acc[1][1]+=a1*b.y; acc[1][2]+=a1*b.z; acc[1][3]+=a1*b.w;
        acc[2][0]+=a2*b.x; acc[2][1]+=a2*b.y; acc[2][2]+=a2*b.z; acc[2][3]+=a2*b.w;
        acc[3][0]+=a3*b.x; acc[3][1]+=a3*b.y; acc[3][2]+=a3*b.z; acc[3][3]+=a3*b.w;
    }

    bool diag = (biB == bjB);
    unsigned w2j[4];
    if (!diag) {
        #pragma unroll
        for (int j = 0; j < 4; j++)
            w2j[j] = cnt[(size_t)(bj + j0 + j) * (NN/4) + (bi >> 2) + ty];
    }

    double sp = 0.0, sw = 0.0;
    #pragma unroll
    for (int e = 0; e < 4; e++) {
        int i = bi + i0 + e;
        unsigned w1 = cnt[(size_t)i * (NN/4) + (bj >> 2) + tx];
        #pragma unroll
        for (int j = 0; j < 4; j++) {
            int jg = bj + j0 + j;
            float z = acc[e][j];
            float ex = __expf(-z);
            float s = __fdividef(1.f, 1.f + ex);
            float logp, log1mp;
            if (z > 15.942384f) {
                logp = -1.1920929e-7f; log1mp = -15.9423847f;
            } else if (z < -16.118095f) {
                logp = -16.118095f;    log1mp = -1.0000000e-7f;
            } else {
                float spv = __logf(1.f + ex);
                logp = -spv; log1mp = -z - spv;
            }
            float ag1 = (float)((w1 >> (j*8)) & 0xFFu) + ((i == jg) ? 1.f : 0.f);
            float wg1 = (ag1 == 1.f) ? PWc : 1.f;
            sp += (double)s;
            sw += (double)(wg1 * (-(ag1 * logp + (1.f - ag1) * log1mp)));
            if (!diag) {
                float ag2 = (float)((w2j[j] >> (e*8)) & 0xFFu);
                float wg2 = (ag2 == 1.f) ? PWc : 1.f;
                sp += (double)s;
                sw += (double)(wg2 * (-(ag2 * logp + (1.f - ag2) * log1mp)));
            }
        }
    }
    __syncthreads();
    double* red = (double*)zsm;
    red[tid] = sp; __syncthreads();
    for (int o = 128; o > 0; o >>= 1) {
        if (tid < o) red[tid] += red[tid + o];
        __syncthreads();
    }
    if (tid == 0) atomicAdd(&accP[bjB], red[0]);
    __syncthreads();
    red[tid] = sw; __syncthreads();
    for (int o = 128; o > 0; o >>= 1) {
        if (tid < o) red[tid] += red[tid + o];
        __syncthreads();
    }
    if (tid == 0) atomicAdd(&accW[bjB], red[0]);
}

__global__ void k_fin(const double* __restrict__ accP, const double* __restrict__ accW,
                      const double* __restrict__ accK, float* __restrict__ out) {
    double sp = 0.0, sw = 0.0, sk = 0.0;
    for (int i = 0; i < 96; i++) { sp += accP[i]; sw += accW[i]; }
    for (int i = 0; i < 64; i++) sk += accK[i];
    double norm = N2D / ((N2D - sp) * 2.0);
    out[BSZ * 100]     = (float)(sk / (double)NN);
    out[BSZ * 100 + 1] = (float)(norm * (sw / N2D));
}

// ---------------- host launch ------------------------------------------------
extern "C" void kernel_launch(void* const* d_in, const int* in_sizes, int n_in,
                              void* d_out, int out_size) {
    const float* user_feats = (const float*)d_in[0];
    const int*   gnf        = (const int*)  d_in[1];
    const int*   eidx       = (const int*)  d_in[2];
    const float* h0         = (const float*)d_in[4];
    const float* eps        = (const float*)d_in[5];
    const float* emb        = (const float*)d_in[6];
    const float* mw1 = (const float*)d_in[7],  *mb1 = (const float*)d_in[8];
    const float* mw2 = (const float*)d_in[9],  *mb2 = (const float*)d_in[10];
    const float* wih0 = (const float*)d_in[11], *whh0 = (const float*)d_in[12];
    const float* bih0 = (const float*)d_in[13], *bhh0 = (const float*)d_in[14];
    const float* wih1 = (const float*)d_in[15], *whh1 = (const float*)d_in[16];
    const float* bih1 = (const float*)d_in[17], *bhh1 = (const float*)d_in[18];
    const float* c1w = (const float*)d_in[19], *c1b = (const float*)d_in[20];
    const float* cmw = (const float*)d_in[21], *cmb = (const float*)d_in[22];
    const float* clw = (const float*)d_in[23], *clb = (const float*)d_in[24];
    float* out = (float*)d_out;
    const int* srcp = eidx;
    const int* dstp = eidx + NEDGE;

    void* p;
    cudaGetSymbolAddress(&p, g_Gi);  float* Gi  = (float*)p;
    cudaGetSymbolAddress(&p, g_Y0);  float* Y0  = (float*)p;
    cudaGetSymbolAddress(&p, g_T1);  float* T1  = (float*)p;
    cudaGetSymbolAddress(&p, g_Xin); float* Xin = (float*)p;
    cudaGetSymbolAddress(&p, g_XW);  float* XW  = (float*)p;
    cudaGetSymbolAddress(&p, g_Hc);  float* Hc  = (float*)p;
    cudaGetSymbolAddress(&p, g_MU);  float* MU  = (float*)p;
    cudaGetSymbolAddress(&p, g_LV);  float* LV  = (float*)p;
    cudaGetSymbolAddress(&p, g_Z);   float* Z   = (float*)p;
    cudaGetSymbolAddress(&p, g_deg); float* deg = (float*)p;
    cudaGetSymbolAddress(&p, g_dis); float* dis = (float*)p;
    cudaGetSymbolAddress(&p, g_Acnt);   unsigned* Acnt = (unsigned*)p;
    cudaGetSymbolAddress(&p, g_accP);   double* accP = (double*)p;
    cudaGetSymbolAddress(&p, g_accW);   double* accW = (double*)p;
    cudaGetSymbolAddress(&p, g_accK);   double* accK = (double*)p;

    cudaFuncSetAttribute(gru_persist<0>, cudaFuncAttributeMaxDynamicSharedMemorySize, GRU_SMEM);
    cudaFuncSetAttribute(gru_persist<1>, cudaFuncAttributeMaxDynamicSharedMemorySize, GRU_SMEM);
    cudaFuncSetAttribute(k_zzt3, cudaFuncAttributeMaxDynamicSharedMemorySize, ZZT_SMEM);

    cudaMemsetAsync(Acnt, 0, (size_t)NN * (NN/4) * sizeof(unsigned));
    cudaMemsetAsync(deg, 0, NN * sizeof(float));
    cudaMemsetAsync(accP, 0, 96 * sizeof(double));
    cudaMemsetAsync(accW, 0, 96 * sizeof(double));
    cudaMemsetAsync(accK, 0, 64 * sizeof(double));

    k_scatter_cnt<<<(NEDGE + 255)/256, 256>>>(srcp, dstp, Acnt, deg);
    k_dis<<<(NN + 255)/256, 256>>>(deg, dis);

    // user encoder MLP -> Xin rows [2048, 4096)
    sgemm3<0><<<dim3(1, 16), 256>>>(user_feats, mw1, mb1, T1, nullptr, nullptr,
                                    NUSR, 100, 9, 1);
    sgemm3<0><<<dim3(1, 16), 256>>>(T1, mw2, mb2, Xin + (size_t)BSZ*100, nullptr, nullptr,
                                    NUSR, 100, 100, 0);

    // E2G = emb @ wih0^T + bih0 (vocab-side precompute)
    sgemm3<1><<<dim3(3, (VOCAB + 127)/128), 256>>>(emb, wih0, bih0, Gi, nullptr, nullptr,
                                                   VOCAB, 300, 300, 0);

    // GRU layer 0
    gru_persist<0><<<128, 256, GRU_SMEM>>>(Gi, gnf, whh0, bhh0, h0, Y0);

    // layer-1 input gates
    sgemm3<1><<<dim3(3, RALL/128), 256>>>(Y0, wih1, bih1, Gi, nullptr, nullptr,
                                          RALL, 300, 100, 0);

    // GRU layer 1 (writes final h scattered into Xin)
    gru_persist<1><<<128, 256, GRU_SMEM>>>(Gi, nullptr, whh1, bhh1,
                                           h0 + (size_t)NTW*HID, Xin);

    // conv1 -> elu (ginit fused into GEMM epilogue)
    sgemm3<0><<<dim3(1, 48), 256>>>(Xin, c1w, c1b, Hc, XW, dis, NN, 64, 100, 0);
    k_gscat<<<(NEDGE*64 + 255)/256, 256>>>(XW, srcp, dstp, dis, Hc, 64);
    k_act<<<(NN*64 + 255)/256, 256>>>(Hc, NN*64, 0);

    // convmu -> relu
    sgemm3<0><<<dim3(1, 48), 256>>>(Hc, cmw, cmb, MU, XW, dis, NN, 100, 64, 0);
    k_gscat<<<(NEDGE*100 + 255)/256, 256>>>(XW, srcp, dstp, dis, MU, 100);
    k_act<<<(NN*100 + 255)/256, 256>>>(MU, NN*100, 1);

    // convlv -> relu
    sgemm3<0><<<dim3(1, 48), 256>>>(Hc, clw, clb, LV, XW, dis, NN, 100, 64, 0);
    k_gscat<<<(NEDGE*100 + 255)/256, 256>>>(XW, srcp, dstp, dis, LV, 100);
    k_act<<<(NN*100 + 255)/256, 256>>>(LV, NN*100, 1);

    k_rep<<<(NN*100 + 255)/256, 256>>>(MU, LV, eps, Z, out);
    k_kl<<<512, 256>>>(MU, LV, accK);
    k_zzt3<<<dim3(96, 96), 256, ZZT_SMEM>>>(Z, Acnt, accP, accW);
    k_fin<<<1, 1>>>(accP, accW, accK, out);
}